// round 1
// baseline (speedup 1.0000x reference)
#include <cuda_runtime.h>
#include <cstdint>

#define NB 4  // batch

// ---------------- static device scratch (allocation-free rule) ----------------
__device__ float g_nx1[NB*2048*3];
__device__ float g_nx2[NB*1024*3];
__device__ float g_nx3[NB*512*3];
__device__ float g_f1[NB*2048*128];
__device__ float g_f2[NB*1024*256];
__device__ float g_f3[NB*512*512];
__device__ int   g_fidx[NB*2048];
__device__ int   g_nidx[NB*2048*64];
__device__ float g_X0[17170432];   // max rows*Cin (stage2: 131072*131)
__device__ float g_YA[33554432];   // max rows*Cout (stage2 L3: 131072*256)
__device__ float g_YB[16777216];

// ---------------- FPS: one block per batch, xyz in SMEM, dist in regs ----------------
template<int BLK, int P>
__global__ __launch_bounds__(BLK)
void fps_kernel(const float* __restrict__ xyz, int N, int npoint, int* __restrict__ fidx)
{
    extern __shared__ float sm[];
    float* sx = sm;
    float* sy = sm + N;
    float* sz = sm + 2*N;
    __shared__ float rv[32];
    __shared__ int   ri[32];
    __shared__ int   s_far;

    const int b = blockIdx.x;
    const int t = threadIdx.x;
    const float* base = xyz + (size_t)b * N * 3;
    for (int i = t; i < N; i += BLK) {
        sx[i] = base[i*3 + 0];
        sy[i] = base[i*3 + 1];
        sz[i] = base[i*3 + 2];
    }
    float dist[P];
#pragma unroll
    for (int k = 0; k < P; k++) dist[k] = 1e10f;
    if (t == 0) { s_far = 0; fidx[(size_t)b*npoint] = 0; }
    __syncthreads();

    for (int j = 1; j < npoint; j++) {
        const int far = s_far;
        const float cx = sx[far], cy = sy[far], cz = sz[far];
        float best = -1.0f; int bidx = 0x7fffffff;
#pragma unroll
        for (int k = 0; k < P; k++) {
            int i = t + k*BLK;
            if (i < N) {
                float dx = sx[i]-cx, dy = sy[i]-cy, dz = sz[i]-cz;
                float d  = dx*dx + dy*dy + dz*dz;
                float nd = fminf(dist[k], d);
                dist[k] = nd;
                if (nd > best) { best = nd; bidx = i; }   // k ascending => first-index kept on ties
            }
        }
        // warp reduce (argmax, min index on tie)
#pragma unroll
        for (int off = 16; off; off >>= 1) {
            float ov = __shfl_down_sync(0xffffffffu, best, off);
            int   oi = __shfl_down_sync(0xffffffffu, bidx, off);
            if (ov > best || (ov == best && oi < bidx)) { best = ov; bidx = oi; }
        }
        int w = t >> 5;
        if ((t & 31) == 0) { rv[w] = best; ri[w] = bidx; }
        __syncthreads();
        if (t < 32) {
            const int nw = BLK / 32;
            float v  = (t < nw) ? rv[t] : -1.0f;
            int   i2 = (t < nw) ? ri[t] : 0x7fffffff;
#pragma unroll
            for (int off = 16; off; off >>= 1) {
                float ov = __shfl_down_sync(0xffffffffu, v,  off);
                int   oi = __shfl_down_sync(0xffffffffu, i2, off);
                if (ov > v || (ov == v && oi < i2)) { v = ov; i2 = oi; }
            }
            if (t == 0) { s_far = i2; fidx[(size_t)b*npoint + j] = i2; }
        }
        __syncthreads();
    }
}

// ---------------- gather new_xyz = xyz[fidx] ----------------
__global__ void gather_xyz(const float* __restrict__ xyz, const int* __restrict__ fidx,
                           float* __restrict__ nxyz, int S, int N, int total)
{
    int idx = blockIdx.x*blockDim.x + threadIdx.x;
    if (idx >= total) return;
    int b = idx / (S*3);
    int r = idx % (S*3);
    int s = r / 3, c = r % 3;
    nxyz[idx] = xyz[((size_t)b*N + fidx[b*S + s])*3 + c];
}

// ---------------- ball query: warp per center, ballot scan ----------------
__global__ void ball_query_kernel(const float* __restrict__ xyz, const float* __restrict__ nxyz,
                                  int* __restrict__ nidx, int S, int N, int nsample,
                                  float r2, int nwarps)
{
    int gw   = (blockIdx.x*blockDim.x + threadIdx.x) >> 5;
    int lane = threadIdx.x & 31;
    if (gw >= nwarps) return;
    int b = gw / S;
    const float* xb = xyz + (size_t)b * N * 3;
    float nx = nxyz[gw*3+0], ny = nxyz[gw*3+1], nz = nxyz[gw*3+2];
    float sn = (nx*nx + ny*ny) + nz*nz;
    int* out = nidx + (size_t)gw * nsample;

    int cnt = 0, first = -1;
    for (int base = 0; base < N; base += 32) {
        int j = base + lane;
        bool in = false;
        if (j < N) {
            float x = xb[j*3+0], y = xb[j*3+1], z = xb[j*3+2];
            float sxx = (x*x + y*y) + z*z;
            float dot = (nx*x + ny*y) + nz*z;
            float d2  = (sn + sxx) - 2.0f*dot;
            in = d2 < r2;
        }
        unsigned m = __ballot_sync(0xffffffffu, in);
        if (in) {
            int pos = cnt + __popc(m & ((1u << lane) - 1u));
            if (pos < nsample) out[pos] = j;
        }
        if (first < 0 && m) first = base + __ffs(m) - 1;
        cnt += __popc(m);
        if (cnt >= nsample) break;
    }
    for (int p = cnt + lane; p < nsample; p += 32) out[p] = first;
}

// ---------------- stage 1 fully fused: group + MLP(3->64->64->128) + maxpool ----------------
#define S1_CPB 4
__global__ __launch_bounds__(128)
void stage1_fused(const float* __restrict__ xyz, const float* __restrict__ nxyz,
                  const int* __restrict__ nidx,
                  const float* __restrict__ w0, const float* __restrict__ b0,
                  const float* __restrict__ w1, const float* __restrict__ b1,
                  const float* __restrict__ w2, const float* __restrict__ b2,
                  float* __restrict__ feats, int S, int N, float radius)
{
    extern __shared__ float smf[];
    float* sW0 = smf;            // 3*64   = 192
    float* sB0 = sW0 + 192;      // 64
    float* sW1 = sB0 + 64;       // 64*64  = 4096
    float* sB1 = sW1 + 4096;     // 64
    float* sW2 = sB1 + 64;       // 64*128 = 8192
    float* sB2 = sW2 + 8192;     // 128
    float* sR  = sB2 + 128;      // 64*3
    float* sH0 = sR  + 192;      // 64*64
    float* sH1 = sH0 + 4096;     // 64*64

    const int t = threadIdx.x;
    for (int i = t; i < 192;  i += 128) sW0[i] = w0[i];
    for (int i = t; i < 64;   i += 128) { sB0[i] = b0[i]; sB1[i] = b1[i]; }
    for (int i = t; i < 4096; i += 128) sW1[i] = w1[i];
    for (int i = t; i < 8192; i += 128) sW2[i] = w2[i];
    for (int i = t; i < 128;  i += 128) sB2[i] = b2[i];
    __syncthreads();

    for (int cc = 0; cc < S1_CPB; cc++) {
        int ctr = blockIdx.x * S1_CPB + cc;
        if (ctr >= NB * S) break;
        int b = ctr / S;
        // phase 0: relative, normalized xyz for 64 neighbors
        if (t < 64) {
            int id = nidx[(size_t)ctr*64 + t];
            const float* p = xyz + ((size_t)b*N + id)*3;
            sR[t*3+0] = (p[0] - nxyz[ctr*3+0]) / radius;
            sR[t*3+1] = (p[1] - nxyz[ctr*3+1]) / radius;
            sR[t*3+2] = (p[2] - nxyz[ctr*3+2]) / radius;
        }
        __syncthreads();
        // phase 1: H0[n][c] = relu(rel . W0[:,c] + b0[c])
#pragma unroll
        for (int jj = 0; jj < 32; jj++) {
            int e = t + jj*128;
            int n = e >> 6, c = e & 63;
            float v = sR[n*3+0]*sW0[c];
            v += sR[n*3+1]*sW0[64+c];
            v += sR[n*3+2]*sW0[128+c];
            v += sB0[c];
            sH0[e] = fmaxf(v, 0.0f);
        }
        __syncthreads();
        // phase 2: H1[n][c] = relu(H0[n] . W1[:,c] + b1[c])
#pragma unroll
        for (int jj = 0; jj < 32; jj++) {
            int e = t + jj*128;
            int n = e >> 6, c = e & 63;
            float acc = 0.0f;
            const float* h = sH0 + n*64;
#pragma unroll 8
            for (int k = 0; k < 64; k++) acc += h[k]*sW1[k*64 + c];
            acc += sB1[c];
            sH1[e] = fmaxf(acc, 0.0f);
        }
        __syncthreads();
        // phase 3: per output channel, H2 over 64 neighbors, fused maxpool
        {
            int c = t;  // 128 threads = 128 channels
            float mx = -3.4e38f;
#pragma unroll 2
            for (int n = 0; n < 64; n++) {
                float acc = 0.0f;
                const float* h = sH1 + n*64;
#pragma unroll 8
                for (int k = 0; k < 64; k++) acc += h[k]*sW2[k*128 + c];
                acc += sB2[c];
                mx = fmaxf(mx, fmaxf(acc, 0.0f));
            }
            feats[(size_t)ctr*128 + c] = mx;
        }
        __syncthreads();
    }
}

// ---------------- group (stages 2-4): X0 = [rel(3) | feats[nidx]] ----------------
__global__ void group_kernel(const float* __restrict__ xyz, const float* __restrict__ nxyz,
                             const int* __restrict__ nidx, const float* __restrict__ feats,
                             float* __restrict__ X0, int S, int N, int ns, int C,
                             float radius, int total)
{
    int idx = blockIdx.x*blockDim.x + threadIdx.x;
    if (idx >= total) return;
    int Cin = 3 + C;
    int row = idx / Cin, c = idx % Cin;
    int b = row / (S*ns);
    int r = row % (S*ns);
    int s = r / ns;
    int id = nidx[row];  // row == (b*S+s)*ns + n
    if (c < 3) {
        X0[idx] = (xyz[((size_t)b*N + id)*3 + c] - nxyz[((size_t)b*S + s)*3 + c]) / radius;
    } else {
        X0[idx] = feats[((size_t)b*N + id)*C + (c - 3)];
    }
}

// ---------------- fp32 GEMM + bias + relu:  Y[M,N] = relu(A[M,K] @ W[K,N] + b) ----------------
// M % 128 == 0, N % 64 == 0, K arbitrary. 256 threads, 8x4 per thread.
__global__ __launch_bounds__(256)
void gemm_bias_relu(const float* __restrict__ A, const float* __restrict__ W,
                    const float* __restrict__ bias, float* __restrict__ Y,
                    int M, int N, int K)
{
    __shared__ __align__(16) float As[8][128];
    __shared__ __align__(16) float Bs[8][64];
    const int bm = blockIdx.y * 128;
    const int bn = blockIdx.x * 64;
    const int t  = threadIdx.x;
    const int tr = (t / 16) * 8;
    const int tc = (t % 16) * 4;
    float acc[8][4];
#pragma unroll
    for (int i = 0; i < 8; i++)
#pragma unroll
        for (int j = 0; j < 4; j++) acc[i][j] = 0.0f;

    for (int k0 = 0; k0 < K; k0 += 8) {
#pragma unroll
        for (int q = 0; q < 4; q++) {
            int e = t*4 + q;
            int ar = e >> 3, ac = e & 7;
            int kk = k0 + ac;
            As[ac][ar] = (kk < K) ? A[(size_t)(bm + ar)*K + kk] : 0.0f;
        }
#pragma unroll
        for (int q = 0; q < 2; q++) {
            int e = t*2 + q;
            int br = e >> 6, bc = e & 63;
            int kk = k0 + br;
            Bs[br][bc] = (kk < K) ? W[(size_t)kk*N + bn + bc] : 0.0f;
        }
        __syncthreads();
#pragma unroll
        for (int kk = 0; kk < 8; kk++) {
            float4 a0 = *reinterpret_cast<const float4*>(&As[kk][tr]);
            float4 a1 = *reinterpret_cast<const float4*>(&As[kk][tr + 4]);
            float4 bb = *reinterpret_cast<const float4*>(&Bs[kk][tc]);
            float av[8] = {a0.x, a0.y, a0.z, a0.w, a1.x, a1.y, a1.z, a1.w};
            float bv[4] = {bb.x, bb.y, bb.z, bb.w};
#pragma unroll
            for (int i = 0; i < 8; i++)
#pragma unroll
                for (int j = 0; j < 4; j++) acc[i][j] += av[i]*bv[j];
        }
        __syncthreads();
    }
#pragma unroll
    for (int i = 0; i < 8; i++) {
        size_t row = (size_t)(bm + tr + i);
#pragma unroll
        for (int j = 0; j < 4; j++) {
            float v = acc[i][j] + bias[bn + tc + j];
            Y[row*N + bn + tc + j] = fmaxf(v, 0.0f);
        }
    }
}

// ---------------- maxpool over nsample rows ----------------
__global__ void maxpool_kernel(const float* __restrict__ Y, float* __restrict__ out,
                               int P, int ns, int C)
{
    int i = blockIdx.x*blockDim.x + threadIdx.x;
    if (i >= P*C) return;
    int p = i / C, c = i % C;
    const float* base = Y + (size_t)p*ns*C + c;
    float m = base[0];
    for (int n = 1; n < ns; n++) m = fmaxf(m, base[(size_t)n*C]);
    out[i] = m;
}

// ---------------- host orchestration ----------------
static inline int cdiv(int a, int b) { return (a + b - 1) / b; }

extern "C" void kernel_launch(void* const* d_in, const int* in_sizes, int n_in,
                              void* d_out, int out_size)
{
    (void)in_sizes; (void)n_in; (void)out_size;
    const float* pc  = (const float*)d_in[0];
    const float* w10 = (const float*)d_in[1],  *b10 = (const float*)d_in[2];
    const float* w11 = (const float*)d_in[3],  *b11 = (const float*)d_in[4];
    const float* w12 = (const float*)d_in[5],  *b12 = (const float*)d_in[6];
    const float* w20 = (const float*)d_in[7],  *b20 = (const float*)d_in[8];
    const float* w21 = (const float*)d_in[9],  *b21 = (const float*)d_in[10];
    const float* w22 = (const float*)d_in[11], *b22 = (const float*)d_in[12];
    const float* w30 = (const float*)d_in[13], *b30 = (const float*)d_in[14];
    const float* w31 = (const float*)d_in[15], *b31 = (const float*)d_in[16];
    const float* w32 = (const float*)d_in[17], *b32 = (const float*)d_in[18];
    const float* w40 = (const float*)d_in[19], *b40 = (const float*)d_in[20];
    const float* w41 = (const float*)d_in[21], *b41 = (const float*)d_in[22];
    const float* w42 = (const float*)d_in[23], *b42 = (const float*)d_in[24];

    float *nx1, *nx2, *nx3, *f1, *f2, *f3, *X0, *YA, *YB;
    int *fidx, *nidx;
    cudaGetSymbolAddress((void**)&nx1,  g_nx1);
    cudaGetSymbolAddress((void**)&nx2,  g_nx2);
    cudaGetSymbolAddress((void**)&nx3,  g_nx3);
    cudaGetSymbolAddress((void**)&f1,   g_f1);
    cudaGetSymbolAddress((void**)&f2,   g_f2);
    cudaGetSymbolAddress((void**)&f3,   g_f3);
    cudaGetSymbolAddress((void**)&X0,   g_X0);
    cudaGetSymbolAddress((void**)&YA,   g_YA);
    cudaGetSymbolAddress((void**)&YB,   g_YB);
    cudaGetSymbolAddress((void**)&fidx, g_fidx);
    cudaGetSymbolAddress((void**)&nidx, g_nidx);

    cudaFuncSetAttribute((const void*)fps_kernel<1024,16>,
                         cudaFuncAttributeMaxDynamicSharedMemorySize, 3*16384*4);
    cudaFuncSetAttribute((const void*)stage1_fused,
                         cudaFuncAttributeMaxDynamicSharedMemorySize, 21120*4);

    float* out = (float*)d_out;
    float* nx4 = out;          // [4,256,3]
    float* f4  = out + 3072;   // [4,256,512]

    // ================= Stage 1: N=16384 -> S=2048, r=0.2, ns=64, MLP 3->64->64->128 =================
    fps_kernel<1024,16><<<NB, 1024, 3*16384*4>>>(pc, 16384, 2048, fidx);
    { int tot = NB*2048*3;
      gather_xyz<<<cdiv(tot,256),256>>>(pc, fidx, nx1, 2048, 16384, tot); }
    { int nw = NB*2048;
      ball_query_kernel<<<cdiv(nw*32,256),256>>>(pc, nx1, nidx, 2048, 16384, 64, (float)(0.2*0.2), nw); }
    stage1_fused<<<cdiv(NB*2048,S1_CPB), 128, 21120*4>>>(pc, nx1, nidx,
        w10,b10,w11,b11,w12,b12, f1, 2048, 16384, 0.2f);

    // ================= Stage 2: N=2048 -> S=1024, r=0.4, ns=32, MLP 131->128->128->256 =================
    fps_kernel<1024,2><<<NB, 1024, 3*2048*4>>>(nx1, 2048, 1024, fidx);
    { int tot = NB*1024*3;
      gather_xyz<<<cdiv(tot,256),256>>>(nx1, fidx, nx2, 1024, 2048, tot); }
    { int nw = NB*1024;
      ball_query_kernel<<<cdiv(nw*32,256),256>>>(nx1, nx2, nidx, 1024, 2048, 32, (float)(0.4*0.4), nw); }
    { int tot = NB*1024*32*131;
      group_kernel<<<cdiv(tot,256),256>>>(nx1, nx2, nidx, f1, X0, 1024, 2048, 32, 128, 0.4f, tot); }
    gemm_bias_relu<<<dim3(128/64, 131072/128), 256>>>(X0, w20, b20, YA, 131072, 128, 131);
    gemm_bias_relu<<<dim3(128/64, 131072/128), 256>>>(YA, w21, b21, YB, 131072, 128, 128);
    gemm_bias_relu<<<dim3(256/64, 131072/128), 256>>>(YB, w22, b22, YA, 131072, 256, 128);
    maxpool_kernel<<<cdiv(NB*1024*256,256),256>>>(YA, f2, NB*1024, 32, 256);

    // ================= Stage 3: N=1024 -> S=512, r=0.6, ns=16, MLP 259->256->256->512 =================
    fps_kernel<1024,1><<<NB, 1024, 3*1024*4>>>(nx2, 1024, 512, fidx);
    { int tot = NB*512*3;
      gather_xyz<<<cdiv(tot,256),256>>>(nx2, fidx, nx3, 512, 1024, tot); }
    { int nw = NB*512;
      ball_query_kernel<<<cdiv(nw*32,256),256>>>(nx2, nx3, nidx, 512, 1024, 16, (float)(0.6*0.6), nw); }
    { int tot = NB*512*16*259;
      group_kernel<<<cdiv(tot,256),256>>>(nx2, nx3, nidx, f2, X0, 512, 1024, 16, 256, 0.6f, tot); }
    gemm_bias_relu<<<dim3(256/64, 32768/128), 256>>>(X0, w30, b30, YA, 32768, 256, 259);
    gemm_bias_relu<<<dim3(256/64, 32768/128), 256>>>(YA, w31, b31, YB, 32768, 256, 256);
    gemm_bias_relu<<<dim3(512/64, 32768/128), 256>>>(YB, w32, b32, YA, 32768, 512, 256);
    maxpool_kernel<<<cdiv(NB*512*512,256),256>>>(YA, f3, NB*512, 16, 512);

    // ================= Stage 4: N=512 -> S=256, r=1.2, ns=8, MLP 515->512->512->512 =================
    fps_kernel<512,1><<<NB, 512, 3*512*4>>>(nx3, 512, 256, fidx);
    { int tot = NB*256*3;
      gather_xyz<<<cdiv(tot,256),256>>>(nx3, fidx, nx4, 256, 512, tot); }
    { int nw = NB*256;
      ball_query_kernel<<<cdiv(nw*32,256),256>>>(nx3, nx4, nidx, 256, 512, 8, (float)(1.2*1.2), nw); }
    { int tot = NB*256*8*515;
      group_kernel<<<cdiv(tot,256),256>>>(nx3, nx4, nidx, f3, X0, 256, 512, 8, 512, 1.2f, tot); }
    gemm_bias_relu<<<dim3(512/64, 8192/128), 256>>>(X0, w40, b40, YA, 8192, 512, 515);
    gemm_bias_relu<<<dim3(512/64, 8192/128), 256>>>(YA, w41, b41, YB, 8192, 512, 512);
    gemm_bias_relu<<<dim3(512/64, 8192/128), 256>>>(YB, w42, b42, YA, 8192, 512, 512);
    maxpool_kernel<<<cdiv(NB*256*512,256),256>>>(YA, f4, NB*256, 8, 512);
}

// round 2
// speedup vs baseline: 1.0003x; 1.0003x over previous
#include <cuda_runtime.h>
#include <cstdint>

#define NB 4  // batch

// ---------------- static device scratch (allocation-free rule) ----------------
__device__ float g_nx1[NB*2048*3];
__device__ float g_nx2[NB*1024*3];
__device__ float g_nx3[NB*512*3];
__device__ float g_f1[NB*2048*128];
__device__ float g_f2[NB*1024*256];
__device__ float g_f3[NB*512*512];
__device__ int   g_fidx[NB*2048];
__device__ int   g_nidx[NB*2048*64];
__device__ float g_X0[17170432];   // max rows*Cin (stage2: 131072*131)
__device__ float g_YA[33554432];   // max rows*Cout (stage2 L3: 131072*256)
__device__ float g_YB[16777216];

// ---------------- FPS: one block per batch, xyz in SMEM, dist in regs ----------------
template<int BLK, int P>
__global__ __launch_bounds__(BLK)
void fps_kernel(const float* __restrict__ xyz, int N, int npoint, int* __restrict__ fidx)
{
    extern __shared__ float sm[];
    float* sx = sm;
    float* sy = sm + N;
    float* sz = sm + 2*N;
    __shared__ float rv[32];
    __shared__ int   ri[32];
    __shared__ int   s_far;

    const int b = blockIdx.x;
    const int t = threadIdx.x;
    const float* base = xyz + (size_t)b * N * 3;
    for (int i = t; i < N; i += BLK) {
        sx[i] = base[i*3 + 0];
        sy[i] = base[i*3 + 1];
        sz[i] = base[i*3 + 2];
    }
    float dist[P];
#pragma unroll
    for (int k = 0; k < P; k++) dist[k] = 1e10f;
    if (t == 0) { s_far = 0; fidx[(size_t)b*npoint] = 0; }
    __syncthreads();

    for (int j = 1; j < npoint; j++) {
        const int far = s_far;
        const float cx = sx[far], cy = sy[far], cz = sz[far];
        float best = -1.0f; int bidx = 0x7fffffff;
#pragma unroll
        for (int k = 0; k < P; k++) {
            int i = t + k*BLK;
            if (i < N) {
                float dx = sx[i]-cx, dy = sy[i]-cy, dz = sz[i]-cz;
                float d  = dx*dx + dy*dy + dz*dz;
                float nd = fminf(dist[k], d);
                dist[k] = nd;
                if (nd > best) { best = nd; bidx = i; }   // k ascending => first-index kept on ties
            }
        }
        // warp reduce (argmax, min index on tie)
#pragma unroll
        for (int off = 16; off; off >>= 1) {
            float ov = __shfl_down_sync(0xffffffffu, best, off);
            int   oi = __shfl_down_sync(0xffffffffu, bidx, off);
            if (ov > best || (ov == best && oi < bidx)) { best = ov; bidx = oi; }
        }
        int w = t >> 5;
        if ((t & 31) == 0) { rv[w] = best; ri[w] = bidx; }
        __syncthreads();
        if (t < 32) {
            const int nw = BLK / 32;
            float v  = (t < nw) ? rv[t] : -1.0f;
            int   i2 = (t < nw) ? ri[t] : 0x7fffffff;
#pragma unroll
            for (int off = 16; off; off >>= 1) {
                float ov = __shfl_down_sync(0xffffffffu, v,  off);
                int   oi = __shfl_down_sync(0xffffffffu, i2, off);
                if (ov > v || (ov == v && oi < i2)) { v = ov; i2 = oi; }
            }
            if (t == 0) { s_far = i2; fidx[(size_t)b*npoint + j] = i2; }
        }
        __syncthreads();
    }
}

// ---------------- gather new_xyz = xyz[fidx] ----------------
__global__ void gather_xyz(const float* __restrict__ xyz, const int* __restrict__ fidx,
                           float* __restrict__ nxyz, int S, int N, int total)
{
    int idx = blockIdx.x*blockDim.x + threadIdx.x;
    if (idx >= total) return;
    int b = idx / (S*3);
    int r = idx % (S*3);
    int s = r / 3, c = r % 3;
    nxyz[idx] = xyz[((size_t)b*N + fidx[b*S + s])*3 + c];
}

// ---------------- ball query: warp per center, ballot scan ----------------
__global__ void ball_query_kernel(const float* __restrict__ xyz, const float* __restrict__ nxyz,
                                  int* __restrict__ nidx, int S, int N, int nsample,
                                  float r2, int nwarps)
{
    int gw   = (blockIdx.x*blockDim.x + threadIdx.x) >> 5;
    int lane = threadIdx.x & 31;
    if (gw >= nwarps) return;
    int b = gw / S;
    const float* xb = xyz + (size_t)b * N * 3;
    float nx = nxyz[gw*3+0], ny = nxyz[gw*3+1], nz = nxyz[gw*3+2];
    float sn = (nx*nx + ny*ny) + nz*nz;
    int* out = nidx + (size_t)gw * nsample;

    int cnt = 0, first = -1;
    for (int base = 0; base < N; base += 32) {
        int j = base + lane;
        bool in = false;
        if (j < N) {
            float x = xb[j*3+0], y = xb[j*3+1], z = xb[j*3+2];
            float sxx = (x*x + y*y) + z*z;
            float dot = (nx*x + ny*y) + nz*z;
            float d2  = (sn + sxx) - 2.0f*dot;
            in = d2 < r2;
        }
        unsigned m = __ballot_sync(0xffffffffu, in);
        if (in) {
            int pos = cnt + __popc(m & ((1u << lane) - 1u));
            if (pos < nsample) out[pos] = j;
        }
        if (first < 0 && m) first = base + __ffs(m) - 1;
        cnt += __popc(m);
        if (cnt >= nsample) break;
    }
    for (int p = cnt + lane; p < nsample; p += 32) out[p] = first;
}

// ---------------- stage 1 fully fused: group + MLP(3->64->64->128) + maxpool ----------------
#define S1_CPB 4
__global__ __launch_bounds__(128)
void stage1_fused(const float* __restrict__ xyz, const float* __restrict__ nxyz,
                  const int* __restrict__ nidx,
                  const float* __restrict__ w0, const float* __restrict__ b0,
                  const float* __restrict__ w1, const float* __restrict__ b1,
                  const float* __restrict__ w2, const float* __restrict__ b2,
                  float* __restrict__ feats, int S, int N, float radius)
{
    extern __shared__ float smf[];
    float* sW0 = smf;            // 3*64   = 192
    float* sB0 = sW0 + 192;      // 64
    float* sW1 = sB0 + 64;       // 64*64  = 4096
    float* sB1 = sW1 + 4096;     // 64
    float* sW2 = sB1 + 64;       // 64*128 = 8192
    float* sB2 = sW2 + 8192;     // 128
    float* sR  = sB2 + 128;      // 64*3
    float* sH0 = sR  + 192;      // 64*64
    float* sH1 = sH0 + 4096;     // 64*64

    const int t = threadIdx.x;
    for (int i = t; i < 192;  i += 128) sW0[i] = w0[i];
    for (int i = t; i < 64;   i += 128) { sB0[i] = b0[i]; sB1[i] = b1[i]; }
    for (int i = t; i < 4096; i += 128) sW1[i] = w1[i];
    for (int i = t; i < 8192; i += 128) sW2[i] = w2[i];
    for (int i = t; i < 128;  i += 128) sB2[i] = b2[i];
    __syncthreads();

    for (int cc = 0; cc < S1_CPB; cc++) {
        int ctr = blockIdx.x * S1_CPB + cc;
        if (ctr >= NB * S) break;
        int b = ctr / S;
        // phase 0: relative, normalized xyz for 64 neighbors
        if (t < 64) {
            int id = nidx[(size_t)ctr*64 + t];
            const float* p = xyz + ((size_t)b*N + id)*3;
            sR[t*3+0] = (p[0] - nxyz[ctr*3+0]) / radius;
            sR[t*3+1] = (p[1] - nxyz[ctr*3+1]) / radius;
            sR[t*3+2] = (p[2] - nxyz[ctr*3+2]) / radius;
        }
        __syncthreads();
        // phase 1: H0[n][c] = relu(rel . W0[:,c] + b0[c])
#pragma unroll
        for (int jj = 0; jj < 32; jj++) {
            int e = t + jj*128;
            int n = e >> 6, c = e & 63;
            float v = sR[n*3+0]*sW0[c];
            v += sR[n*3+1]*sW0[64+c];
            v += sR[n*3+2]*sW0[128+c];
            v += sB0[c];
            sH0[e] = fmaxf(v, 0.0f);
        }
        __syncthreads();
        // phase 2: H1[n][c] = relu(H0[n] . W1[:,c] + b1[c])
#pragma unroll
        for (int jj = 0; jj < 32; jj++) {
            int e = t + jj*128;
            int n = e >> 6, c = e & 63;
            float acc = 0.0f;
            const float* h = sH0 + n*64;
#pragma unroll 8
            for (int k = 0; k < 64; k++) acc += h[k]*sW1[k*64 + c];
            acc += sB1[c];
            sH1[e] = fmaxf(acc, 0.0f);
        }
        __syncthreads();
        // phase 3: per output channel, H2 over 64 neighbors, fused maxpool
        {
            int c = t;  // 128 threads = 128 channels
            float mx = -3.4e38f;
#pragma unroll 2
            for (int n = 0; n < 64; n++) {
                float acc = 0.0f;
                const float* h = sH1 + n*64;
#pragma unroll 8
                for (int k = 0; k < 64; k++) acc += h[k]*sW2[k*128 + c];
                acc += sB2[c];
                mx = fmaxf(mx, fmaxf(acc, 0.0f));
            }
            feats[(size_t)ctr*128 + c] = mx;
        }
        __syncthreads();
    }
}

// ---------------- group (stages 2-4): X0 = [rel(3) | feats[nidx]] ----------------
__global__ void group_kernel(const float* __restrict__ xyz, const float* __restrict__ nxyz,
                             const int* __restrict__ nidx, const float* __restrict__ feats,
                             float* __restrict__ X0, int S, int N, int ns, int C,
                             float radius, int total)
{
    int idx = blockIdx.x*blockDim.x + threadIdx.x;
    if (idx >= total) return;
    int Cin = 3 + C;
    int row = idx / Cin, c = idx % Cin;
    int b = row / (S*ns);
    int r = row % (S*ns);
    int s = r / ns;
    int id = nidx[row];  // row == (b*S+s)*ns + n
    if (c < 3) {
        X0[idx] = (xyz[((size_t)b*N + id)*3 + c] - nxyz[((size_t)b*S + s)*3 + c]) / radius;
    } else {
        X0[idx] = feats[((size_t)b*N + id)*C + (c - 3)];
    }
}

// ---------------- fp32 GEMM + bias + relu:  Y[M,N] = relu(A[M,K] @ W[K,N] + b) ----------------
// M % 128 == 0, N % 64 == 0, K arbitrary. 256 threads, 8x4 per thread.
__global__ __launch_bounds__(256)
void gemm_bias_relu(const float* __restrict__ A, const float* __restrict__ W,
                    const float* __restrict__ bias, float* __restrict__ Y,
                    int M, int N, int K)
{
    __shared__ __align__(16) float As[8][128];
    __shared__ __align__(16) float Bs[8][64];
    const int bm = blockIdx.y * 128;
    const int bn = blockIdx.x * 64;
    const int t  = threadIdx.x;
    const int tr = (t / 16) * 8;
    const int tc = (t % 16) * 4;
    float acc[8][4];
#pragma unroll
    for (int i = 0; i < 8; i++)
#pragma unroll
        for (int j = 0; j < 4; j++) acc[i][j] = 0.0f;

    for (int k0 = 0; k0 < K; k0 += 8) {
#pragma unroll
        for (int q = 0; q < 4; q++) {
            int e = t*4 + q;
            int ar = e >> 3, ac = e & 7;
            int kk = k0 + ac;
            As[ac][ar] = (kk < K) ? A[(size_t)(bm + ar)*K + kk] : 0.0f;
        }
#pragma unroll
        for (int q = 0; q < 2; q++) {
            int e = t*2 + q;
            int br = e >> 6, bc = e & 63;
            int kk = k0 + br;
            Bs[br][bc] = (kk < K) ? W[(size_t)kk*N + bn + bc] : 0.0f;
        }
        __syncthreads();
#pragma unroll
        for (int kk = 0; kk < 8; kk++) {
            float4 a0 = *reinterpret_cast<const float4*>(&As[kk][tr]);
            float4 a1 = *reinterpret_cast<const float4*>(&As[kk][tr + 4]);
            float4 bb = *reinterpret_cast<const float4*>(&Bs[kk][tc]);
            float av[8] = {a0.x, a0.y, a0.z, a0.w, a1.x, a1.y, a1.z, a1.w};
            float bv[4] = {bb.x, bb.y, bb.z, bb.w};
#pragma unroll
            for (int i = 0; i < 8; i++)
#pragma unroll
                for (int j = 0; j < 4; j++) acc[i][j] += av[i]*bv[j];
        }
        __syncthreads();
    }
#pragma unroll
    for (int i = 0; i < 8; i++) {
        size_t row = (size_t)(bm + tr + i);
#pragma unroll
        for (int j = 0; j < 4; j++) {
            float v = acc[i][j] + bias[bn + tc + j];
            Y[row*N + bn + tc + j] = fmaxf(v, 0.0f);
        }
    }
}

// ---------------- maxpool over nsample rows ----------------
__global__ void maxpool_kernel(const float* __restrict__ Y, float* __restrict__ out,
                               int P, int ns, int C)
{
    int i = blockIdx.x*blockDim.x + threadIdx.x;
    if (i >= P*C) return;
    int p = i / C, c = i % C;
    const float* base = Y + (size_t)p*ns*C + c;
    float m = base[0];
    for (int n = 1; n < ns; n++) m = fmaxf(m, base[(size_t)n*C]);
    out[i] = m;
}

// ---------------- host orchestration ----------------
static inline int cdiv(int a, int b) { return (a + b - 1) / b; }

extern "C" void kernel_launch(void* const* d_in, const int* in_sizes, int n_in,
                              void* d_out, int out_size)
{
    (void)in_sizes; (void)n_in; (void)out_size;
    const float* pc  = (const float*)d_in[0];
    const float* w10 = (const float*)d_in[1],  *b10 = (const float*)d_in[2];
    const float* w11 = (const float*)d_in[3],  *b11 = (const float*)d_in[4];
    const float* w12 = (const float*)d_in[5],  *b12 = (const float*)d_in[6];
    const float* w20 = (const float*)d_in[7],  *b20 = (const float*)d_in[8];
    const float* w21 = (const float*)d_in[9],  *b21 = (const float*)d_in[10];
    const float* w22 = (const float*)d_in[11], *b22 = (const float*)d_in[12];
    const float* w30 = (const float*)d_in[13], *b30 = (const float*)d_in[14];
    const float* w31 = (const float*)d_in[15], *b31 = (const float*)d_in[16];
    const float* w32 = (const float*)d_in[17], *b32 = (const float*)d_in[18];
    const float* w40 = (const float*)d_in[19], *b40 = (const float*)d_in[20];
    const float* w41 = (const float*)d_in[21], *b41 = (const float*)d_in[22];
    const float* w42 = (const float*)d_in[23], *b42 = (const float*)d_in[24];

    float *nx1, *nx2, *nx3, *f1, *f2, *f3, *X0, *YA, *YB;
    int *fidx, *nidx;
    cudaGetSymbolAddress((void**)&nx1,  g_nx1);
    cudaGetSymbolAddress((void**)&nx2,  g_nx2);
    cudaGetSymbolAddress((void**)&nx3,  g_nx3);
    cudaGetSymbolAddress((void**)&f1,   g_f1);
    cudaGetSymbolAddress((void**)&f2,   g_f2);
    cudaGetSymbolAddress((void**)&f3,   g_f3);
    cudaGetSymbolAddress((void**)&X0,   g_X0);
    cudaGetSymbolAddress((void**)&YA,   g_YA);
    cudaGetSymbolAddress((void**)&YB,   g_YB);
    cudaGetSymbolAddress((void**)&fidx, g_fidx);
    cudaGetSymbolAddress((void**)&nidx, g_nidx);

    cudaFuncSetAttribute((const void*)fps_kernel<1024,16>,
                         cudaFuncAttributeMaxDynamicSharedMemorySize, 3*16384*4);
    cudaFuncSetAttribute((const void*)stage1_fused,
                         cudaFuncAttributeMaxDynamicSharedMemorySize, 21120*4);

    float* out = (float*)d_out;
    float* nx4 = out;          // [4,256,3]
    float* f4  = out + 3072;   // [4,256,512]

    // ================= Stage 1: N=16384 -> S=2048, r=0.2, ns=64, MLP 3->64->64->128 =================
    fps_kernel<1024,16><<<NB, 1024, 3*16384*4>>>(pc, 16384, 2048, fidx);
    { int tot = NB*2048*3;
      gather_xyz<<<cdiv(tot,256),256>>>(pc, fidx, nx1, 2048, 16384, tot); }
    { int nw = NB*2048;
      ball_query_kernel<<<cdiv(nw*32,256),256>>>(pc, nx1, nidx, 2048, 16384, 64, (float)(0.2*0.2), nw); }
    stage1_fused<<<cdiv(NB*2048,S1_CPB), 128, 21120*4>>>(pc, nx1, nidx,
        w10,b10,w11,b11,w12,b12, f1, 2048, 16384, 0.2f);

    // ================= Stage 2: N=2048 -> S=1024, r=0.4, ns=32, MLP 131->128->128->256 =================
    fps_kernel<1024,2><<<NB, 1024, 3*2048*4>>>(nx1, 2048, 1024, fidx);
    { int tot = NB*1024*3;
      gather_xyz<<<cdiv(tot,256),256>>>(nx1, fidx, nx2, 1024, 2048, tot); }
    { int nw = NB*1024;
      ball_query_kernel<<<cdiv(nw*32,256),256>>>(nx1, nx2, nidx, 1024, 2048, 32, (float)(0.4*0.4), nw); }
    { int tot = NB*1024*32*131;
      group_kernel<<<cdiv(tot,256),256>>>(nx1, nx2, nidx, f1, X0, 1024, 2048, 32, 128, 0.4f, tot); }
    gemm_bias_relu<<<dim3(128/64, 131072/128), 256>>>(X0, w20, b20, YA, 131072, 128, 131);
    gemm_bias_relu<<<dim3(128/64, 131072/128), 256>>>(YA, w21, b21, YB, 131072, 128, 128);
    gemm_bias_relu<<<dim3(256/64, 131072/128), 256>>>(YB, w22, b22, YA, 131072, 256, 128);
    maxpool_kernel<<<cdiv(NB*1024*256,256),256>>>(YA, f2, NB*1024, 32, 256);

    // ================= Stage 3: N=1024 -> S=512, r=0.6, ns=16, MLP 259->256->256->512 =================
    fps_kernel<1024,1><<<NB, 1024, 3*1024*4>>>(nx2, 1024, 512, fidx);
    { int tot = NB*512*3;
      gather_xyz<<<cdiv(tot,256),256>>>(nx2, fidx, nx3, 512, 1024, tot); }
    { int nw = NB*512;
      ball_query_kernel<<<cdiv(nw*32,256),256>>>(nx2, nx3, nidx, 512, 1024, 16, (float)(0.6*0.6), nw); }
    { int tot = NB*512*16*259;
      group_kernel<<<cdiv(tot,256),256>>>(nx2, nx3, nidx, f2, X0, 512, 1024, 16, 256, 0.6f, tot); }
    gemm_bias_relu<<<dim3(256/64, 32768/128), 256>>>(X0, w30, b30, YA, 32768, 256, 259);
    gemm_bias_relu<<<dim3(256/64, 32768/128), 256>>>(YA, w31, b31, YB, 32768, 256, 256);
    gemm_bias_relu<<<dim3(512/64, 32768/128), 256>>>(YB, w32, b32, YA, 32768, 512, 256);
    maxpool_kernel<<<cdiv(NB*512*512,256),256>>>(YA, f3, NB*512, 16, 512);

    // ================= Stage 4: N=512 -> S=256, r=1.2, ns=8, MLP 515->512->512->512 =================
    fps_kernel<512,1><<<NB, 512, 3*512*4>>>(nx3, 512, 256, fidx);
    { int tot = NB*256*3;
      gather_xyz<<<cdiv(tot,256),256>>>(nx3, fidx, nx4, 256, 512, tot); }
    { int nw = NB*256;
      ball_query_kernel<<<cdiv(nw*32,256),256>>>(nx3, nx4, nidx, 256, 512, 8, (float)(1.2*1.2), nw); }
    { int tot = NB*256*8*515;
      group_kernel<<<cdiv(tot,256),256>>>(nx3, nx4, nidx, f3, X0, 256, 512, 8, 512, 1.2f, tot); }
    gemm_bias_relu<<<dim3(512/64, 8192/128), 256>>>(X0, w40, b40, YA, 8192, 512, 515);
    gemm_bias_relu<<<dim3(512/64, 8192/128), 256>>>(YA, w41, b41, YB, 8192, 512, 512);
    gemm_bias_relu<<<dim3(512/64, 8192/128), 256>>>(YB, w42, b42, YA, 8192, 512, 512);
    maxpool_kernel<<<cdiv(NB*256*512,256),256>>>(YA, f4, NB*256, 8, 512);
}

// round 3
// speedup vs baseline: 1.2904x; 1.2899x over previous
#include <cuda_runtime.h>
#include <cstdint>

#define NB 4
typedef unsigned long long ull;

__device__ __forceinline__ ull pk2(float lo, float hi) {
    ull r; asm("mov.b64 %0, {%1, %2};" : "=l"(r) : "f"(lo), "f"(hi)); return r;
}
__device__ __forceinline__ void upk2(ull v, float& a, float& b) {
    asm("mov.b64 {%0, %1}, %2;" : "=f"(a), "=f"(b) : "l"(v));
}
__device__ __forceinline__ ull add2(ull a, ull b) {
    ull r; asm("add.rn.f32x2 %0, %1, %2;" : "=l"(r) : "l"(a), "l"(b)); return r;
}
__device__ __forceinline__ ull mul2(ull a, ull b) {
    ull r; asm("mul.rn.f32x2 %0, %1, %2;" : "=l"(r) : "l"(a), "l"(b)); return r;
}
__device__ __forceinline__ ull fma2(ull a, ull b, ull c) {
    ull r; asm("fma.rn.f32x2 %0, %1, %2, %3;" : "=l"(r) : "l"(a), "l"(b), "l"(c)); return r;
}

__device__ float g_nx1[NB*2048*3];
__device__ float g_nx2[NB*1024*3];
__device__ float g_nx3[NB*512*3];
__device__ float g_f1[NB*2048*128];
__device__ float g_f2[NB*1024*256];
__device__ float g_f3[NB*512*512];
__device__ int   g_fidx[NB*2048];
__device__ int   g_nidx[NB*2048*64];
__device__ float g_X0[17170432];
__device__ float g_YA[33554432];
__device__ float g_YB[16777216];

// ============ FPS stage 1: N=16384, y/z in regs (f32x2), x from smem ============
__global__ __launch_bounds__(512)
void fps1_kernel(const float* __restrict__ xyz, int* __restrict__ fidx)
{
    const int N = 16384, NP = 2048, BLK = 512;
    extern __shared__ float sm[];
    float* sx = sm; float* sy = sm + N; float* sz = sm + 2*N;
    __shared__ float rv[16];
    __shared__ float s_gmax;
    __shared__ int   s_idx;
    __shared__ float s_cx, s_cy, s_cz;

    const int b = blockIdx.x, t = threadIdx.x;
    const int lane = t & 31, w = t >> 5;
    const float* base = xyz + (size_t)b * N * 3;

    ull py2[16], pz2[16];
    float dst[32];
    for (int i = t; i < N; i += BLK) {
        sx[i] = base[i*3+0]; sy[i] = base[i*3+1]; sz[i] = base[i*3+2];
    }
#pragma unroll
    for (int k = 0; k < 16; k++) {
        int i0 = 2*(t + k*BLK);
        py2[k] = pk2(base[i0*3+1], base[i0*3+4]);
        pz2[k] = pk2(base[i0*3+2], base[i0*3+5]);
        dst[2*k] = 1e10f; dst[2*k+1] = 1e10f;
    }
    if (t == 0) {
        s_cx = base[0]; s_cy = base[1]; s_cz = base[2];
        fidx[(size_t)b*NP] = 0;
    }
    __syncthreads();

    for (int j = 1; j < NP; j++) {
        const float cx = s_cx, cy = s_cy, cz = s_cz;
        const ull ncx = pk2(-cx,-cx), ncy = pk2(-cy,-cy), ncz = pk2(-cz,-cz);
        float tb = -1.0f;
#pragma unroll
        for (int k = 0; k < 16; k++) {
            int p = t + k*BLK;
            ull xp = *(const ull*)&sx[2*p];
            ull dx = add2(xp, ncx);
            ull dy = add2(py2[k], ncy);
            ull dz = add2(pz2[k], ncz);
            ull s  = mul2(dx, dx);
            s = fma2(dy, dy, s);
            s = fma2(dz, dz, s);
            float d0, d1; upk2(s, d0, d1);
            float n0 = fminf(dst[2*k],   d0); dst[2*k]   = n0;
            float n1 = fminf(dst[2*k+1], d1); dst[2*k+1] = n1;
            tb = fmaxf(tb, fmaxf(n0, n1));
        }
        float wv = tb;
#pragma unroll
        for (int off = 16; off; off >>= 1)
            wv = fmaxf(wv, __shfl_xor_sync(0xffffffffu, wv, off));
        if (lane == 0) rv[w] = wv;
        __syncthreads();
        if (t == 0) s_idx = 0x7fffffff;
        if (t < 32) {
            float v = (t < 16) ? rv[t] : -1.0f;
#pragma unroll
            for (int off = 16; off; off >>= 1)
                v = fmaxf(v, __shfl_xor_sync(0xffffffffu, v, off));
            if (t == 0) s_gmax = v;
        }
        __syncthreads();
        const float gm = s_gmax;
        int mi = 0x7fffffff;
        if (tb == gm) {
#pragma unroll
            for (int k2 = 0; k2 < 32; k2++)
                if (dst[k2] == gm) mi = min(mi, 2*t + (k2 >> 1)*1024 + (k2 & 1));
        }
#pragma unroll
        for (int off = 16; off; off >>= 1)
            mi = min(mi, __shfl_xor_sync(0xffffffffu, mi, off));
        if (lane == 0 && mi != 0x7fffffff) atomicMin(&s_idx, mi);
        __syncthreads();
        if (t == 0) {
            int far = s_idx;
            fidx[(size_t)b*NP + j] = far;
            s_cx = sx[far]; s_cy = sy[far]; s_cz = sz[far];
        }
        __syncthreads();
    }
}

// ============ FPS stages 2-4: coords fully in registers ============
template<int BLK, int P>
__global__ __launch_bounds__(BLK)
void fps_reg_kernel(const float* __restrict__ xyz, int npoint, int* __restrict__ fidx)
{
    const int N = BLK * P;
    extern __shared__ float sm[];
    float* sx = sm; float* sy = sm + N; float* sz = sm + 2*N;
    __shared__ float rv[32];
    __shared__ int   ri[32];
    __shared__ float s_cx, s_cy, s_cz;

    const int b = blockIdx.x, t = threadIdx.x;
    const float* base = xyz + (size_t)b * N * 3;
    float px[P], py[P], pz[P], dst[P];
#pragma unroll
    for (int k = 0; k < P; k++) {
        int i = t + k*BLK;
        px[k] = base[i*3+0]; py[k] = base[i*3+1]; pz[k] = base[i*3+2];
        sx[i] = px[k]; sy[i] = py[k]; sz[i] = pz[k];
        dst[k] = 1e10f;
    }
    if (t == 0) {
        s_cx = px[0]; s_cy = py[0]; s_cz = pz[0];
        fidx[(size_t)b*npoint] = 0;
    }
    __syncthreads();

    for (int j = 1; j < npoint; j++) {
        const float cx = s_cx, cy = s_cy, cz = s_cz;
        float best = -1.0f; int bi = 0x7fffffff;
#pragma unroll
        for (int k = 0; k < P; k++) {
            float dx = px[k]-cx, dy = py[k]-cy, dz = pz[k]-cz;
            float nd = fminf(dst[k], dx*dx + dy*dy + dz*dz);
            dst[k] = nd;
            if (nd > best) { best = nd; bi = t + k*BLK; }
        }
#pragma unroll
        for (int off = 16; off; off >>= 1) {
            float ov = __shfl_down_sync(0xffffffffu, best, off);
            int   oi = __shfl_down_sync(0xffffffffu, bi,   off);
            if (ov > best || (ov == best && oi < bi)) { best = ov; bi = oi; }
        }
        int w = t >> 5;
        if ((t & 31) == 0) { rv[w] = best; ri[w] = bi; }
        __syncthreads();
        if (t < 32) {
            const int nw = BLK / 32;
            float v  = (t < nw) ? rv[t] : -1.0f;
            int   i2 = (t < nw) ? ri[t] : 0x7fffffff;
#pragma unroll
            for (int off = 16; off; off >>= 1) {
                float ov = __shfl_down_sync(0xffffffffu, v,  off);
                int   oi = __shfl_down_sync(0xffffffffu, i2, off);
                if (ov > v || (ov == v && oi < i2)) { v = ov; i2 = oi; }
            }
            if (t == 0) {
                fidx[(size_t)b*npoint + j] = i2;
                s_cx = sx[i2]; s_cy = sy[i2]; s_cz = sz[i2];
            }
        }
        __syncthreads();
    }
}

__global__ void gather_xyz(const float* __restrict__ xyz, const int* __restrict__ fidx,
                           float* __restrict__ nxyz, int S, int N, int total)
{
    int idx = blockIdx.x*blockDim.x + threadIdx.x;
    if (idx >= total) return;
    int b = idx / (S*3);
    int r = idx % (S*3);
    int s = r / 3, c = r % 3;
    nxyz[idx] = xyz[((size_t)b*N + fidx[b*S + s])*3 + c];
}

__global__ void ball_query_kernel(const float* __restrict__ xyz, const float* __restrict__ nxyz,
                                  int* __restrict__ nidx, int S, int N, int nsample,
                                  float r2, int nwarps)
{
    int gw   = (blockIdx.x*blockDim.x + threadIdx.x) >> 5;
    int lane = threadIdx.x & 31;
    if (gw >= nwarps) return;
    int b = gw / S;
    const float* xb = xyz + (size_t)b * N * 3;
    float nx = nxyz[gw*3+0], ny = nxyz[gw*3+1], nz = nxyz[gw*3+2];
    float sn = (nx*nx + ny*ny) + nz*nz;
    int* out = nidx + (size_t)gw * nsample;

    int cnt = 0, first = -1;
    for (int base = 0; base < N; base += 32) {
        int j = base + lane;
        bool in = false;
        if (j < N) {
            float x = xb[j*3+0], y = xb[j*3+1], z = xb[j*3+2];
            float sxx = (x*x + y*y) + z*z;
            float dot = (nx*x + ny*y) + nz*z;
            in = ((sn + sxx) - 2.0f*dot) < r2;
        }
        unsigned m = __ballot_sync(0xffffffffu, in);
        if (in) {
            int pos = cnt + __popc(m & ((1u << lane) - 1u));
            if (pos < nsample) out[pos] = j;
        }
        if (first < 0 && m) first = base + __ffs(m) - 1;
        cnt += __popc(m);
        if (cnt >= nsample) break;
    }
    for (int p = cnt + lane; p < nsample; p += 32) out[p] = first;
}

// ============ stage 1 fused: group + MLP(3->64->64->128) + maxpool ============
#define SA1_SMEM 21120
__global__ __launch_bounds__(128)
void sa1_kernel(const float* __restrict__ xyz, const float* __restrict__ nxyz,
                const int* __restrict__ nidx,
                const float* __restrict__ w0, const float* __restrict__ b0,
                const float* __restrict__ w1, const float* __restrict__ b1,
                const float* __restrict__ w2, const float* __restrict__ b2,
                float* __restrict__ feats, float radius)
{
    extern __shared__ float sm[];
    float* sW0 = sm;              // 192
    float* sB0 = sm + 192;        // 64
    float* sW1 = sm + 256;        // 4096
    float* sB1 = sm + 4352;       // 64
    float* sW2 = sm + 4416;       // 8192
    float* sB2 = sm + 12608;      // 128
    float* sR  = sm + 12736;      // 192
    float* sH0 = sm + 12928;      // 64x64 transposed [c][n]
    float* sH1 = sm + 17024;      // 64x64 transposed [c][n]

    const int t = threadIdx.x;
    const int ctr = blockIdx.x;
    const int b = ctr >> 11;

    for (int i = t; i < 192;  i += 128) sW0[i] = w0[i];
    if (t < 64) { sB0[t] = b0[t]; sB1[t] = b1[t]; }
    for (int i = t; i < 4096; i += 128) sW1[i] = w1[i];
    for (int i = t; i < 8192; i += 128) sW2[i] = w2[i];
    sB2[t] = b2[t];
    if (t < 64) {
        int id = nidx[(size_t)ctr*64 + t];
        const float* p = xyz + ((size_t)(b << 14) + id)*3;
        sR[t*3+0] = (p[0] - nxyz[ctr*3+0]) / radius;
        sR[t*3+1] = (p[1] - nxyz[ctr*3+1]) / radius;
        sR[t*3+2] = (p[2] - nxyz[ctr*3+2]) / radius;
    }
    __syncthreads();

    // layer 1 -> sH0[c][n]
    {
        int n = t & 63, half = t >> 6;
        float rx = sR[n*3+0], ry = sR[n*3+1], rz = sR[n*3+2];
#pragma unroll 8
        for (int cc = 0; cc < 32; cc++) {
            int c = half*32 + cc;
            float v = sB0[c] + rx*sW0[c] + ry*sW0[64+c] + rz*sW0[128+c];
            sH0[c*64 + n] = fmaxf(v, 0.0f);
        }
    }
    __syncthreads();

    const int ng = t & 15, cg = t >> 4;
    float acc[32];

    // layer 2: 4n x 8c tile
#pragma unroll
    for (int i = 0; i < 4; i++)
#pragma unroll
        for (int jj = 0; jj < 8; jj++) acc[i*8+jj] = sB1[8*cg + jj];
#pragma unroll 8
    for (int k = 0; k < 64; k++) {
        float4 a = *(const float4*)&sH0[k*64 + 4*ng];
        float4 u = *(const float4*)&sW1[k*64 + 8*cg];
        float4 v = *(const float4*)&sW1[k*64 + 8*cg + 4];
        float av[4] = {a.x, a.y, a.z, a.w};
        float bv[8] = {u.x, u.y, u.z, u.w, v.x, v.y, v.z, v.w};
#pragma unroll
        for (int i = 0; i < 4; i++)
#pragma unroll
            for (int jj = 0; jj < 8; jj++) acc[i*8+jj] += av[i]*bv[jj];
    }
#pragma unroll
    for (int jj = 0; jj < 8; jj++) {
        float4 o;
        o.x = fmaxf(acc[0*8+jj], 0.0f);
        o.y = fmaxf(acc[1*8+jj], 0.0f);
        o.z = fmaxf(acc[2*8+jj], 0.0f);
        o.w = fmaxf(acc[3*8+jj], 0.0f);
        *(float4*)&sH1[(8*cg+jj)*64 + 4*ng] = o;
    }
    __syncthreads();

    // layer 3 + fused maxpool (two 64-channel passes)
#pragma unroll 1
    for (int pass = 0; pass < 2; pass++) {
        int c0 = pass*64 + 8*cg;
#pragma unroll
        for (int i = 0; i < 4; i++)
#pragma unroll
            for (int jj = 0; jj < 8; jj++) acc[i*8+jj] = sB2[c0 + jj];
#pragma unroll 8
        for (int k = 0; k < 64; k++) {
            float4 a = *(const float4*)&sH1[k*64 + 4*ng];
            float4 u = *(const float4*)&sW2[k*128 + c0];
            float4 v = *(const float4*)&sW2[k*128 + c0 + 4];
            float av[4] = {a.x, a.y, a.z, a.w};
            float bv[8] = {u.x, u.y, u.z, u.w, v.x, v.y, v.z, v.w};
#pragma unroll
            for (int i = 0; i < 4; i++)
#pragma unroll
                for (int jj = 0; jj < 8; jj++) acc[i*8+jj] += av[i]*bv[jj];
        }
#pragma unroll
        for (int jj = 0; jj < 8; jj++) {
            float m = fmaxf(fmaxf(fmaxf(acc[0*8+jj], 0.0f), fmaxf(acc[1*8+jj], 0.0f)),
                            fmaxf(fmaxf(acc[2*8+jj], 0.0f), fmaxf(acc[3*8+jj], 0.0f)));
#pragma unroll
            for (int off = 8; off; off >>= 1)
                m = fmaxf(m, __shfl_xor_sync(0xffffffffu, m, off));
            if (ng == 0) feats[(size_t)ctr*128 + c0 + jj] = m;
        }
    }
}

__global__ void group_kernel(const float* __restrict__ xyz, const float* __restrict__ nxyz,
                             const int* __restrict__ nidx, const float* __restrict__ feats,
                             float* __restrict__ X0, int S, int N, int ns, int C,
                             float radius, int total)
{
    int idx = blockIdx.x*blockDim.x + threadIdx.x;
    if (idx >= total) return;
    int Cin = 3 + C;
    int row = idx / Cin, c = idx % Cin;
    int b = row / (S*ns);
    int r = row % (S*ns);
    int s = r / ns;
    int id = nidx[row];
    if (c < 3) {
        X0[idx] = (xyz[((size_t)b*N + id)*3 + c] - nxyz[((size_t)b*S + s)*3 + c]) / radius;
    } else {
        X0[idx] = feats[((size_t)b*N + id)*C + (c - 3)];
    }
}

// ============ fp32 GEMM + bias + relu: 128x128 tile, 8x8 micro ============
__global__ __launch_bounds__(256)
void gemm128(const float* __restrict__ A, const float* __restrict__ W,
             const float* __restrict__ bias, float* __restrict__ Y,
             int M, int N, int K)
{
    __shared__ __align__(16) float As[8][128];
    __shared__ __align__(16) float Bs[8][128];
    const int bm = blockIdx.y * 128;
    const int bn = blockIdx.x * 128;
    const int t  = threadIdx.x;
    const int ty = t >> 4, tx = t & 15;
    float acc[8][8];
#pragma unroll
    for (int i = 0; i < 8; i++)
#pragma unroll
        for (int j = 0; j < 8; j++) acc[i][j] = 0.0f;

    const int abr = t >> 5;
    const int abc = (t & 31) * 4;

    for (int k0 = 0; k0 < K; k0 += 8) {
#pragma unroll
        for (int q = 0; q < 4; q++) {
            int e = t*4 + q;
            int ar = e >> 3, ac = e & 7;
            int kk = k0 + ac;
            As[ac][ar] = (kk < K) ? A[(size_t)(bm + ar)*K + kk] : 0.0f;
        }
        {
            int kk = k0 + abr;
            float4 wv = make_float4(0.f, 0.f, 0.f, 0.f);
            if (kk < K) wv = *(const float4*)&W[(size_t)kk*N + bn + abc];
            *(float4*)&Bs[abr][abc] = wv;
        }
        __syncthreads();
#pragma unroll
        for (int kk = 0; kk < 8; kk++) {
            float4 a0 = *(const float4*)&As[kk][ty*8];
            float4 a1 = *(const float4*)&As[kk][ty*8 + 4];
            float4 b0 = *(const float4*)&Bs[kk][tx*8];
            float4 b1 = *(const float4*)&Bs[kk][tx*8 + 4];
            float av[8] = {a0.x, a0.y, a0.z, a0.w, a1.x, a1.y, a1.z, a1.w};
            float bv[8] = {b0.x, b0.y, b0.z, b0.w, b1.x, b1.y, b1.z, b1.w};
#pragma unroll
            for (int i = 0; i < 8; i++)
#pragma unroll
                for (int j = 0; j < 8; j++) acc[i][j] += av[i]*bv[j];
        }
        __syncthreads();
    }
    float4 bb0 = *(const float4*)&bias[bn + tx*8];
    float4 bb1 = *(const float4*)&bias[bn + tx*8 + 4];
    float bv[8] = {bb0.x, bb0.y, bb0.z, bb0.w, bb1.x, bb1.y, bb1.z, bb1.w};
#pragma unroll
    for (int i = 0; i < 8; i++) {
        size_t row = (size_t)(bm + ty*8 + i);
        float4 o0, o1;
        o0.x = fmaxf(acc[i][0]+bv[0], 0.f); o0.y = fmaxf(acc[i][1]+bv[1], 0.f);
        o0.z = fmaxf(acc[i][2]+bv[2], 0.f); o0.w = fmaxf(acc[i][3]+bv[3], 0.f);
        o1.x = fmaxf(acc[i][4]+bv[4], 0.f); o1.y = fmaxf(acc[i][5]+bv[5], 0.f);
        o1.z = fmaxf(acc[i][6]+bv[6], 0.f); o1.w = fmaxf(acc[i][7]+bv[7], 0.f);
        *(float4*)&Y[row*N + bn + tx*8]     = o0;
        *(float4*)&Y[row*N + bn + tx*8 + 4] = o1;
    }
}

__global__ void maxpool_kernel(const float* __restrict__ Y, float* __restrict__ out,
                               int P, int ns, int C)
{
    int i = blockIdx.x*blockDim.x + threadIdx.x;
    if (i >= P*C) return;
    int p = i / C, c = i % C;
    const float* base = Y + (size_t)p*ns*C + c;
    float m = base[0];
    for (int n = 1; n < ns; n++) m = fmaxf(m, base[(size_t)n*C]);
    out[i] = m;
}

static inline int cdiv(int a, int b) { return (a + b - 1) / b; }

extern "C" void kernel_launch(void* const* d_in, const int* in_sizes, int n_in,
                              void* d_out, int out_size)
{
    (void)in_sizes; (void)n_in; (void)out_size;
    const float* pc  = (const float*)d_in[0];
    const float* w10 = (const float*)d_in[1],  *b10 = (const float*)d_in[2];
    const float* w11 = (const float*)d_in[3],  *b11 = (const float*)d_in[4];
    const float* w12 = (const float*)d_in[5],  *b12 = (const float*)d_in[6];
    const float* w20 = (const float*)d_in[7],  *b20 = (const float*)d_in[8];
    const float* w21 = (const float*)d_in[9],  *b21 = (const float*)d_in[10];
    const float* w22 = (const float*)d_in[11], *b22 = (const float*)d_in[12];
    const float* w30 = (const float*)d_in[13], *b30 = (const float*)d_in[14];
    const float* w31 = (const float*)d_in[15], *b31 = (const float*)d_in[16];
    const float* w32 = (const float*)d_in[17], *b32 = (const float*)d_in[18];
    const float* w40 = (const float*)d_in[19], *b40 = (const float*)d_in[20];
    const float* w41 = (const float*)d_in[21], *b41 = (const float*)d_in[22];
    const float* w42 = (const float*)d_in[23], *b42 = (const float*)d_in[24];

    float *nx1, *nx2, *nx3, *f1, *f2, *f3, *X0, *YA, *YB;
    int *fidx, *nidx;
    cudaGetSymbolAddress((void**)&nx1,  g_nx1);
    cudaGetSymbolAddress((void**)&nx2,  g_nx2);
    cudaGetSymbolAddress((void**)&nx3,  g_nx3);
    cudaGetSymbolAddress((void**)&f1,   g_f1);
    cudaGetSymbolAddress((void**)&f2,   g_f2);
    cudaGetSymbolAddress((void**)&f3,   g_f3);
    cudaGetSymbolAddress((void**)&X0,   g_X0);
    cudaGetSymbolAddress((void**)&YA,   g_YA);
    cudaGetSymbolAddress((void**)&YB,   g_YB);
    cudaGetSymbolAddress((void**)&fidx, g_fidx);
    cudaGetSymbolAddress((void**)&nidx, g_nidx);

    cudaFuncSetAttribute((const void*)fps1_kernel,
                         cudaFuncAttributeMaxDynamicSharedMemorySize, 3*16384*4);
    cudaFuncSetAttribute((const void*)sa1_kernel,
                         cudaFuncAttributeMaxDynamicSharedMemorySize, SA1_SMEM*4);

    float* out = (float*)d_out;
    float* nx4 = out;          // [4,256,3]
    float* f4  = out + 3072;   // [4,256,512]

    // Stage 1: 16384 -> 2048, r=0.2, ns=64
    fps1_kernel<<<NB, 512, 3*16384*4>>>(pc, fidx);
    gather_xyz<<<cdiv(NB*2048*3,256),256>>>(pc, fidx, nx1, 2048, 16384, NB*2048*3);
    ball_query_kernel<<<cdiv(NB*2048*32,256),256>>>(pc, nx1, nidx, 2048, 16384, 64, 0.04f, NB*2048);
    sa1_kernel<<<NB*2048, 128, SA1_SMEM*4>>>(pc, nx1, nidx, w10,b10,w11,b11,w12,b12, f1, 0.2f);

    // Stage 2: 2048 -> 1024, r=0.4, ns=32, MLP 131->128->128->256
    fps_reg_kernel<512,4><<<NB, 512, 3*2048*4>>>(nx1, 1024, fidx);
    gather_xyz<<<cdiv(NB*1024*3,256),256>>>(nx1, fidx, nx2, 1024, 2048, NB*1024*3);
    ball_query_kernel<<<cdiv(NB*1024*32,256),256>>>(nx1, nx2, nidx, 1024, 2048, 32, 0.16f, NB*1024);
    group_kernel<<<cdiv(NB*1024*32*131,256),256>>>(nx1, nx2, nidx, f1, X0, 1024, 2048, 32, 128, 0.4f, NB*1024*32*131);
    gemm128<<<dim3(1, 1024), 256>>>(X0, w20, b20, YA, 131072, 128, 131);
    gemm128<<<dim3(1, 1024), 256>>>(YA, w21, b21, YB, 131072, 128, 128);
    gemm128<<<dim3(2, 1024), 256>>>(YB, w22, b22, YA, 131072, 256, 128);
    maxpool_kernel<<<cdiv(NB*1024*256,256),256>>>(YA, f2, NB*1024, 32, 256);

    // Stage 3: 1024 -> 512, r=0.6, ns=16, MLP 259->256->256->512
    fps_reg_kernel<256,4><<<NB, 256, 3*1024*4>>>(nx2, 512, fidx);
    gather_xyz<<<cdiv(NB*512*3,256),256>>>(nx2, fidx, nx3, 512, 1024, NB*512*3);
    ball_query_kernel<<<cdiv(NB*512*32,256),256>>>(nx2, nx3, nidx, 512, 1024, 16, 0.36f, NB*512);
    group_kernel<<<cdiv(NB*512*16*259,256),256>>>(nx2, nx3, nidx, f2, X0, 512, 1024, 16, 256, 0.6f, NB*512*16*259);
    gemm128<<<dim3(2, 256), 256>>>(X0, w30, b30, YA, 32768, 256, 259);
    gemm128<<<dim3(2, 256), 256>>>(YA, w31, b31, YB, 32768, 256, 256);
    gemm128<<<dim3(4, 256), 256>>>(YB, w32, b32, YA, 32768, 512, 256);
    maxpool_kernel<<<cdiv(NB*512*512,256),256>>>(YA, f3, NB*512, 16, 512);

    // Stage 4: 512 -> 256, r=1.2, ns=8, MLP 515->512->512->512
    fps_reg_kernel<128,4><<<NB, 128, 3*512*4>>>(nx3, 256, fidx);
    gather_xyz<<<cdiv(NB*256*3,256),256>>>(nx3, fidx, nx4, 256, 512, NB*256*3);
    ball_query_kernel<<<cdiv(NB*256*32,256),256>>>(nx3, nx4, nidx, 256, 512, 8, 1.44f, NB*256);
    group_kernel<<<cdiv(NB*256*8*515,256),256>>>(nx3, nx4, nidx, f3, X0, 256, 512, 8, 512, 1.2f, NB*256*8*515);
    gemm128<<<dim3(4, 64), 256>>>(X0, w40, b40, YA, 8192, 512, 515);
    gemm128<<<dim3(4, 64), 256>>>(YA, w41, b41, YB, 8192, 512, 512);
    gemm128<<<dim3(4, 64), 256>>>(YB, w42, b42, YA, 8192, 512, 512);
    maxpool_kernel<<<cdiv(NB*256*512,256),256>>>(YA, f4, NB*256, 8, 512);
}